// round 1
// baseline (speedup 1.0000x reference)
#include <cuda_runtime.h>
#include <cstdint>
#include <cstddef>

#define BATCH 4
#define NPTS  4096
#define PTOT  (BATCH*NPTS)     /* 16384 */
#define KNN   16
#define EDGES (PTOT*KNN)       /* 262144 */
#define FLTMAX 3.402823466e+38f

// ---------------- scratch (__device__ globals; no allocs allowed) ----------------
__device__ int      d_idx[EDGES];          // global target index per edge
__device__ float    d_Ap[PTOT*64];         // per-point source term (BN folded)
__device__ float    d_Cp[PTOT*64];         // per-point neighbor term (gamma folded)
__device__ float    d_h2buf[(size_t)EDGES*128];
__device__ unsigned d_xenc[PTOT*256];      // scatter-max, monotonic-uint encoded
__device__ float    d_g1[PTOT*256];
__device__ float    d_g2[PTOT*512];
__device__ unsigned d_scene[BATCH*1024];   // global max pool, encoded

// monotonic float<->uint encoding (order-preserving for atomicMax)
__device__ __forceinline__ unsigned encf(float f){
    unsigned u = __float_as_uint(f);
    return (u & 0x80000000u) ? ~u : (u | 0x80000000u);
}
__device__ __forceinline__ float decf(unsigned u){
    return __uint_as_float((u & 0x80000000u) ? (u ^ 0x80000000u) : ~u);
}

// ---------------- init ----------------
__global__ void init_kernel(){
    int i = blockIdx.x * 256 + threadIdx.x;
    if (i < PTOT*256)   d_xenc[i]  = 0x00800000u;  // enc(-FLT_MAX)
    if (i < BATCH*1024) d_scene[i] = 0x00800000u;
}

// ---------------- kNN: one warp per source point, cloud in smem ----------------
__global__ __launch_bounds__(256) void knn_kernel(const float* __restrict__ pos){
    __shared__ float sbuf[3*NPTS];   // 48KB: phase1 = x|y|z cloud; phase2 reused for merge lists
    float* sx = sbuf;
    float* sy = sbuf + NPTS;
    float* sz = sbuf + 2*NPTS;

    int b  = blockIdx.x >> 9;          // 512 blocks per batch (8 sources each)
    int s0 = (blockIdx.x & 511) * 8;
    const float* pb = pos + (size_t)b * NPTS * 3;
    for (int i = threadIdx.x; i < NPTS; i += 256){
        sx[i] = pb[3*i]; sy[i] = pb[3*i+1]; sz[i] = pb[3*i+2];
    }
    __syncthreads();

    int w = threadIdx.x >> 5, lane = threadIdx.x & 31;
    int src = s0 + w;
    float qx = sx[src], qy = sy[src], qz = sz[src];

    float ld[KNN]; int li[KNN];
#pragma unroll
    for (int j = 0; j < KNN; j++){ ld[j] = FLTMAX; li[j] = 1<<30; }

    for (int c = lane; c < NPTS; c += 32){
        float dx = qx - sx[c], dy = qy - sy[c], dz = qz - sz[c];
        // match reference rounding: no fma contraction, left-assoc sum
        float d = __fadd_rn(__fadd_rn(__fmul_rn(dx,dx), __fmul_rn(dy,dy)), __fmul_rn(dz,dz));
        if (d < ld[KNN-1] || (d == ld[KNN-1] && c < li[KNN-1])){
            ld[KNN-1] = d; li[KNN-1] = c;
#pragma unroll
            for (int j = KNN-1; j > 0; j--){
                bool sw = (ld[j] < ld[j-1]) || (ld[j] == ld[j-1] && li[j] < li[j-1]);
                if (sw){
                    float td = ld[j]; ld[j] = ld[j-1]; ld[j-1] = td;
                    int   ti = li[j]; li[j] = li[j-1]; li[j-1] = ti;
                }
            }
        }
    }

    __syncthreads();                     // cloud no longer needed; reuse smem
    float* smd = sbuf;                   // 4096 floats
    int*   smi = (int*)(sbuf + 4096);    // 4096 ints
    int base = (w*32 + lane) * KNN;
#pragma unroll
    for (int j = 0; j < KNN; j++){ smd[base+j] = ld[j]; smi[base+j] = li[j]; }
    __syncwarp();

    int ptr = 0;
    int outbase = (b*NPTS + src) * KNN;
    for (int r = 0; r < KNN; r++){
        float myd = (ptr < KNN) ? smd[base+ptr] : FLTMAX;
        int   myi = (ptr < KNN) ? smi[base+ptr] : (1<<30);
        float bd = myd; int bi = myi;
#pragma unroll
        for (int off = 16; off; off >>= 1){
            float od = __shfl_xor_sync(0xffffffffu, bd, off);
            int   oi = __shfl_xor_sync(0xffffffffu, bi, off);
            if (od < bd || (od == bd && oi < bi)){ bd = od; bi = oi; }
        }
        if (myd == bd && myi == bi) ptr++;   // candidate indices unique -> one winner
        if (lane == 0) d_idx[outbase + r] = b*NPTS + bi;
    }
}

// ---------------- fold layer-1 + BN into per-point A'/C' ----------------
__global__ void prep_ac(const float* __restrict__ pos, const float* __restrict__ cw1,
                        const float* __restrict__ cb1, const float* __restrict__ cg1,
                        const float* __restrict__ cs1){
    int gi = blockIdx.x * 256 + threadIdx.x;   // PTOT*64
    int p = gi >> 6, j = gi & 63;
    float x = pos[p*3], y = pos[p*3+1], z = pos[p*3+2];
    float w0 = cw1[0*64+j] + cw1[3*64+j];
    float w1 = cw1[1*64+j] + cw1[4*64+j];
    float w2 = cw1[2*64+j] + cw1[5*64+j];
    float a = fmaf(x, w0, fmaf(y, w1, fmaf(z, w2, cb1[j])));
    float c = fmaf(x, cw1[3*64+j], fmaf(y, cw1[4*64+j], z*cw1[5*64+j]));
    float g = cg1[j];
    d_Ap[gi] = fmaf(a, g, cs1[j]);
    d_Cp[gi] = c * g;
}

// ---------------- generic tiled SGEMM with fused A-gen + epilogues ----------------
// MODE 1: h2 = relu(bn(edge_h1 @ cw2))         M=EDGES N=128  K=64
// MODE 2: m  = h2 @ cw3 + b ; scatter-max      M=EDGES N=256  K=128
// MODE 3: g1 = relu(bn(g0 @ sw1))              M=PTOT  N=256  K=259
// MODE 4: g2 = relu(bn(g1 @ sw2))              M=PTOT  N=512  K=256
// MODE 5: g3 = g2 @ sw3 + b ; scene-max        M=PTOT  N=1024 K=512
template<int MODE>
__global__ __launch_bounds__(256) void gemm_k(
    const float* __restrict__ Bw, const float* __restrict__ bias,
    const float* __restrict__ gamma, const float* __restrict__ beta,
    const float* __restrict__ pos)
{
    constexpr int Nt = (MODE==1)?128:(MODE==2)?256:(MODE==3)?256:(MODE==4)?512:1024;
    constexpr int Kt = (MODE==1)?64:(MODE==2)?128:(MODE==3)?259:(MODE==4)?256:512;
    constexpr int BM = 128, BN = 128, BK = 16;

    __shared__ alignas(16) float As[BK][BM];
    __shared__ alignas(16) float Bs[BK][BN];

    const int m0 = blockIdx.y * BM;
    const int n0 = blockIdx.x * BN;
    const int tid = threadIdx.x;
    const int tx = tid & 15, ty = tid >> 4;
    const int arow = tid >> 1;         // 0..127
    const int ac0  = (tid & 1) * 8;    // 0 or 8
    const int brow = tid >> 4;         // 0..15
    const int bc0  = (tid & 15) * 8;
    const int am = m0 + arow;

    const float*    ap1 = nullptr;
    const float*    ap2 = nullptr;
    const unsigned* apx = nullptr;
    if constexpr (MODE == 1){ ap1 = d_Ap + (am >> 4) * 64; ap2 = d_Cp + d_idx[am] * 64; }
    else if constexpr (MODE == 2){ ap1 = d_h2buf + (size_t)am * 128; }
    else if constexpr (MODE == 3){ apx = d_xenc + am * 256; ap1 = pos + am * 3; }
    else if constexpr (MODE == 4){ ap1 = d_g1 + am * 256; }
    else { ap1 = d_g2 + (size_t)am * 512; }

    float acc[8][8];
#pragma unroll
    for (int i = 0; i < 8; i++)
#pragma unroll
        for (int j = 0; j < 8; j++) acc[i][j] = 0.f;

    constexpr int NKT = (Kt + BK - 1) / BK;
    for (int kt = 0; kt < NKT; kt++){
        const int k0 = kt * BK;
#pragma unroll
        for (int j = 0; j < 8; j++){
            int k = k0 + ac0 + j;
            float v;
            if constexpr (MODE == 1){
                v = fmaxf(ap1[k] - ap2[k], 0.f);
            } else if constexpr (MODE == 3){
                if (k < 256)      v = decf(apx[k]);
                else if (k < Kt)  v = ap1[k - 256];
                else              v = 0.f;
            } else {
                v = ap1[k];
            }
            As[ac0 + j][arow] = v;
        }
#pragma unroll
        for (int j = 0; j < 8; j++){
            int k = k0 + brow;
            float v;
            if constexpr (Kt % BK != 0) v = (k < Kt) ? Bw[k * Nt + n0 + bc0 + j] : 0.f;
            else                        v = Bw[k * Nt + n0 + bc0 + j];
            Bs[brow][bc0 + j] = v;
        }
        __syncthreads();
#pragma unroll
        for (int kk = 0; kk < BK; kk++){
            float a[8], bfr[8];
            *(float4*)&a[0]   = *(const float4*)&As[kk][ty*8];
            *(float4*)&a[4]   = *(const float4*)&As[kk][ty*8 + 4];
            *(float4*)&bfr[0] = *(const float4*)&Bs[kk][tx*8];
            *(float4*)&bfr[4] = *(const float4*)&Bs[kk][tx*8 + 4];
#pragma unroll
            for (int i = 0; i < 8; i++)
#pragma unroll
                for (int j = 0; j < 8; j++)
                    acc[i][j] = fmaf(a[i], bfr[j], acc[i][j]);
        }
        __syncthreads();
    }

    if constexpr (MODE == 1 || MODE == 3 || MODE == 4){
        float bi[8], ga[8], be[8];
#pragma unroll
        for (int j = 0; j < 8; j++){
            int n = n0 + tx*8 + j;
            bi[j] = bias[n]; ga[j] = gamma[n]; be[j] = beta[n];
        }
        float* Cout;
        if constexpr (MODE == 1) Cout = d_h2buf;
        else if constexpr (MODE == 3) Cout = d_g1;
        else Cout = d_g2;
#pragma unroll
        for (int i = 0; i < 8; i++){
            int m = m0 + ty*8 + i;
#pragma unroll
            for (int j = 0; j < 8; j++){
                int n = n0 + tx*8 + j;
                float v = fmaf(acc[i][j] + bi[j], ga[j], be[j]);
                Cout[(size_t)m * Nt + n] = fmaxf(v, 0.f);
            }
        }
    } else if constexpr (MODE == 2){
        float bi[8];
#pragma unroll
        for (int j = 0; j < 8; j++) bi[j] = bias[n0 + tx*8 + j];
#pragma unroll
        for (int i = 0; i < 8; i++){
            int m = m0 + ty*8 + i;
            int tgt = d_idx[m];
            unsigned* xp = d_xenc + tgt * 256 + n0 + tx*8;
#pragma unroll
            for (int j = 0; j < 8; j++)
                atomicMax(&xp[j], encf(acc[i][j] + bi[j]));
        }
    } else { // MODE 5: block column-max then one atomic per column
        float cm[8];
#pragma unroll
        for (int j = 0; j < 8; j++){
            float mv = acc[0][j];
#pragma unroll
            for (int i = 1; i < 8; i++) mv = fmaxf(mv, acc[i][j]);
            cm[j] = mv + bias[n0 + tx*8 + j];
        }
        __syncthreads();
#pragma unroll
        for (int j = 0; j < 8; j++) As[ty][tx*8 + j] = cm[j];
        __syncthreads();
        if (tid < 128){
            float mv = As[0][tid];
#pragma unroll
            for (int r = 1; r < 16; r++) mv = fmaxf(mv, As[r][tid]);
            int bb = m0 >> 12;   // 4096 points per batch, BM=128 divides it
            atomicMax(&d_scene[bb * 1024 + n0 + tid], encf(mv));
        }
    }
}

// ---------------- final predictor MLP: one block per batch ----------------
__global__ __launch_bounds__(256) void predictor(
    const int* __restrict__ qidx,
    const float* __restrict__ pw1, const float* __restrict__ pb1,
    const float* __restrict__ pw2, const float* __restrict__ pb2,
    const float* __restrict__ pw3, const float* __restrict__ pb3,
    float* __restrict__ out)
{
    __shared__ float ef[1280];
    __shared__ float h1[512];
    __shared__ float h2[256];
    int b = blockIdx.x, tid = threadIdx.x;
    int q = b * NPTS + qidx[b];

    if (tid < 256) ef[tid] = decf(d_xenc[q * 256 + tid]);
    for (int i = tid; i < 1024; i += 256) ef[256 + i] = decf(d_scene[b * 1024 + i]);
    __syncthreads();

    for (int o = tid; o < 512; o += 256){
        float s = pb1[o];
#pragma unroll 4
        for (int k = 0; k < 1280; k++) s = fmaf(ef[k], pw1[k*512 + o], s);
        h1[o] = fmaxf(s, 0.f);
    }
    __syncthreads();
    {
        int o = tid;
        float s = pb2[o];
#pragma unroll 4
        for (int k = 0; k < 512; k++) s = fmaf(h1[k], pw2[k*256 + o], s);
        h2[o] = fmaxf(s, 0.f);
    }
    __syncthreads();
    if (tid < 16){
        float s = pb3[tid];
#pragma unroll 4
        for (int k = 0; k < 256; k++) s = fmaf(h2[k], pw3[k*16 + tid], s);
        out[b*16 + tid] = s;
    }
}

// ---------------- launch ----------------
extern "C" void kernel_launch(void* const* d_in, const int* in_sizes, int n_in,
                              void* d_out, int out_size)
{
    const float* pos  = (const float*)d_in[0];
    const int*   qidx = (const int*)  d_in[1];
    const float* cw1 = (const float*)d_in[2];
    const float* cb1 = (const float*)d_in[3];
    const float* cg1 = (const float*)d_in[4];
    const float* cs1 = (const float*)d_in[5];
    const float* cw2 = (const float*)d_in[6];
    const float* cb2 = (const float*)d_in[7];
    const float* cg2 = (const float*)d_in[8];
    const float* cs2 = (const float*)d_in[9];
    const float* cw3 = (const float*)d_in[10];
    const float* cb3 = (const float*)d_in[11];
    const float* sw1 = (const float*)d_in[12];
    const float* sb1 = (const float*)d_in[13];
    const float* sg1 = (const float*)d_in[14];
    const float* ss1 = (const float*)d_in[15];
    const float* sw2 = (const float*)d_in[16];
    const float* sb2 = (const float*)d_in[17];
    const float* sg2 = (const float*)d_in[18];
    const float* ss2 = (const float*)d_in[19];
    const float* sw3 = (const float*)d_in[20];
    const float* sb3 = (const float*)d_in[21];
    const float* pw1 = (const float*)d_in[22];
    const float* pb1 = (const float*)d_in[23];
    const float* pw2 = (const float*)d_in[24];
    const float* pb2 = (const float*)d_in[25];
    const float* pw3 = (const float*)d_in[26];
    const float* pb3 = (const float*)d_in[27];

    init_kernel<<<(PTOT*256 + 255)/256, 256>>>();
    knn_kernel<<<PTOT/8, 256>>>(pos);
    prep_ac<<<(PTOT*64)/256, 256>>>(pos, cw1, cb1, cg1, cs1);

    gemm_k<1><<<dim3(1,    EDGES/128), 256>>>(cw2, cb2, cg2, cs2, nullptr);
    gemm_k<2><<<dim3(2,    EDGES/128), 256>>>(cw3, cb3, nullptr, nullptr, nullptr);
    gemm_k<3><<<dim3(2,    PTOT/128),  256>>>(sw1, sb1, sg1, ss1, pos);
    gemm_k<4><<<dim3(4,    PTOT/128),  256>>>(sw2, sb2, sg2, ss2, nullptr);
    gemm_k<5><<<dim3(8,    PTOT/128),  256>>>(sw3, sb3, nullptr, nullptr, nullptr);

    predictor<<<BATCH, 256>>>(qidx, pw1, pb1, pw2, pb2, pw3, pb3, (float*)d_out);
}

// round 2
// speedup vs baseline: 1.3339x; 1.3339x over previous
#include <cuda_runtime.h>
#include <cstdint>
#include <cstddef>

#define BATCH 4
#define NPTS  4096
#define PTOT  (BATCH*NPTS)     /* 16384 */
#define KNN   16
#define EDGES (PTOT*KNN)       /* 262144 */
#define FLTMAX 3.402823466e+38f

// ---------------- scratch ----------------
__device__ int      d_idx[EDGES];
__device__ float    d_Ap[PTOT*64];
__device__ float    d_Cp[PTOT*64];
__device__ float    d_h2buf[(size_t)EDGES*128];
__device__ unsigned d_xenc[PTOT*256];
__device__ float    d_g1[PTOT*256];
__device__ float    d_g2[PTOT*512];
__device__ unsigned d_scene[BATCH*1024];
__device__ float    d_ph1[BATCH*512];

__device__ __forceinline__ unsigned encf(float f){
    unsigned u = __float_as_uint(f);
    return (u & 0x80000000u) ? ~u : (u | 0x80000000u);
}
__device__ __forceinline__ float decf(unsigned u){
    return __uint_as_float((u & 0x80000000u) ? (u ^ 0x80000000u) : ~u);
}

__device__ __forceinline__ void cp_async16(void* smem, const void* gmem, unsigned sz){
    unsigned s = (unsigned)__cvta_generic_to_shared(smem);
    asm volatile("cp.async.cg.shared.global [%0], [%1], 16, %2;\n" :: "r"(s), "l"(gmem), "r"(sz));
}
__device__ __forceinline__ void cp_commit(){ asm volatile("cp.async.commit_group;\n"); }
__device__ __forceinline__ void cp_wait0(){ asm volatile("cp.async.wait_group 0;\n"); }

// ---------------- init ----------------
__global__ void init_kernel(){
    int i = blockIdx.x * 256 + threadIdx.x;
    if (i < PTOT*256)   d_xenc[i]  = 0x00800000u;
    if (i < BATCH*1024) d_scene[i] = 0x00800000u;
}

// ---------------- kNN ----------------
__global__ __launch_bounds__(256) void knn_kernel(const float* __restrict__ pos){
    __shared__ float sbuf[3*NPTS];
    float* sx = sbuf;
    float* sy = sbuf + NPTS;
    float* sz = sbuf + 2*NPTS;

    int b  = blockIdx.x >> 9;
    int s0 = (blockIdx.x & 511) * 8;
    const float* pb = pos + (size_t)b * NPTS * 3;
    for (int i = threadIdx.x; i < NPTS; i += 256){
        sx[i] = pb[3*i]; sy[i] = pb[3*i+1]; sz[i] = pb[3*i+2];
    }
    __syncthreads();

    int w = threadIdx.x >> 5, lane = threadIdx.x & 31;
    int src = s0 + w;
    float qx = sx[src], qy = sy[src], qz = sz[src];

    float ld[KNN]; int li[KNN];
#pragma unroll
    for (int j = 0; j < KNN; j++){ ld[j] = FLTMAX; li[j] = 1<<30; }

    for (int c = lane; c < NPTS; c += 32){
        float dx = qx - sx[c], dy = qy - sy[c], dz = qz - sz[c];
        float d = __fadd_rn(__fadd_rn(__fmul_rn(dx,dx), __fmul_rn(dy,dy)), __fmul_rn(dz,dz));
        if (d < ld[KNN-1] || (d == ld[KNN-1] && c < li[KNN-1])){
            ld[KNN-1] = d; li[KNN-1] = c;
#pragma unroll
            for (int j = KNN-1; j > 0; j--){
                bool sw = (ld[j] < ld[j-1]) || (ld[j] == ld[j-1] && li[j] < li[j-1]);
                if (sw){
                    float td = ld[j]; ld[j] = ld[j-1]; ld[j-1] = td;
                    int   ti = li[j]; li[j] = li[j-1]; li[j-1] = ti;
                }
            }
        }
    }

    __syncthreads();
    float* smd = sbuf;
    int*   smi = (int*)(sbuf + 4096);
    int base = (w*32 + lane) * KNN;
#pragma unroll
    for (int j = 0; j < KNN; j++){ smd[base+j] = ld[j]; smi[base+j] = li[j]; }
    __syncwarp();

    int ptr = 0;
    int outbase = (b*NPTS + src) * KNN;
    for (int r = 0; r < KNN; r++){
        float myd = (ptr < KNN) ? smd[base+ptr] : FLTMAX;
        int   myi = (ptr < KNN) ? smi[base+ptr] : (1<<30);
        float bd = myd; int bi = myi;
#pragma unroll
        for (int off = 16; off; off >>= 1){
            float od = __shfl_xor_sync(0xffffffffu, bd, off);
            int   oi = __shfl_xor_sync(0xffffffffu, bi, off);
            if (od < bd || (od == bd && oi < bi)){ bd = od; bi = oi; }
        }
        if (myd == bd && myi == bi) ptr++;
        if (lane == 0) d_idx[outbase + r] = b*NPTS + bi;
    }
}

// ---------------- fold layer-1 + BN ----------------
__global__ void prep_ac(const float* __restrict__ pos, const float* __restrict__ cw1,
                        const float* __restrict__ cb1, const float* __restrict__ cg1,
                        const float* __restrict__ cs1){
    int gi = blockIdx.x * 256 + threadIdx.x;
    int p = gi >> 6, j = gi & 63;
    float x = pos[p*3], y = pos[p*3+1], z = pos[p*3+2];
    float w0 = cw1[0*64+j] + cw1[3*64+j];
    float w1 = cw1[1*64+j] + cw1[4*64+j];
    float w2 = cw1[2*64+j] + cw1[5*64+j];
    float a = fmaf(x, w0, fmaf(y, w1, fmaf(z, w2, cb1[j])));
    float c = fmaf(x, cw1[3*64+j], fmaf(y, cw1[4*64+j], z*cw1[5*64+j]));
    float g = cg1[j];
    d_Ap[gi] = fmaf(a, g, cs1[j]);
    d_Cp[gi] = c * g;
}

// ---------------- pipelined SGEMM with fused A-gen + epilogues ----------------
// MODE 1: h2 = relu(bn(edge_h1 @ cw2))         M=EDGES N=128  K=64
// MODE 2: m  = h2 @ cw3 + b ; scatter-max      M=EDGES N=256  K=128
// MODE 3: g1 = relu(bn(g0 @ sw1))              M=PTOT  N=256  K=259
// MODE 4: g2 = relu(bn(g1 @ sw2))              M=PTOT  N=512  K=256
// MODE 5: g3 = g2 @ sw3 + b ; scene-max        M=PTOT  N=1024 K=512
template<int MODE>
__global__ __launch_bounds__(256, 2) void gemm_k(
    const float* __restrict__ Bw, const float* __restrict__ bias,
    const float* __restrict__ gamma, const float* __restrict__ beta,
    const float* __restrict__ pos)
{
    constexpr int Nt = (MODE==1)?128:(MODE==2)?256:(MODE==3)?256:(MODE==4)?512:1024;
    constexpr int Kt = (MODE==1)?64:(MODE==2)?128:(MODE==3)?259:(MODE==4)?256:512;
    constexpr int BM = 128, BN = 128, BK = 16;
    constexpr int NKT = (Kt + BK - 1) / BK;

    __shared__ alignas(16) float As[2][BK][BM];
    __shared__ alignas(16) float Bs[2][BK][BN];

    const int m0 = blockIdx.y * BM;
    const int n0 = blockIdx.x * BN;
    const int tid = threadIdx.x;
    const int tx = tid & 15, ty = tid >> 4;

    // A staging mapping: one row per thread, 8 consecutive k per tile
    const int am  = m0 + (tid >> 1);
    const int kb  = (tid & 1) * 8;
    const int m_l = tid >> 1;

    const float*    ap1 = nullptr;
    const float*    ap2 = nullptr;
    const unsigned* apx = nullptr;
    if constexpr (MODE == 1){ ap1 = d_Ap + (am >> 4) * 64; ap2 = d_Cp + d_idx[am] * 64; }
    else if constexpr (MODE == 2){ ap1 = d_h2buf + (size_t)am * 128; }
    else if constexpr (MODE == 3){ apx = d_xenc + am * 256; ap1 = pos + am * 3; }
    else if constexpr (MODE == 4){ ap1 = d_g1 + am * 256; }
    else { ap1 = d_g2 + (size_t)am * 512; }

    float ra[8], rc[8];   // A staging registers (rc only MODE 1)

    auto fetchA = [&](int kt){
        const int k = kt * BK + kb;
        if constexpr (MODE == 1){
            *(float4*)&ra[0] = *(const float4*)(ap1 + k);
            *(float4*)&ra[4] = *(const float4*)(ap1 + k + 4);
            *(float4*)&rc[0] = *(const float4*)(ap2 + k);
            *(float4*)&rc[4] = *(const float4*)(ap2 + k + 4);
        } else if constexpr (MODE == 3){
            if (k + 7 < 256){
                uint4 u0 = *(const uint4*)(apx + k);
                uint4 u1 = *(const uint4*)(apx + k + 4);
                ra[0]=decf(u0.x); ra[1]=decf(u0.y); ra[2]=decf(u0.z); ra[3]=decf(u0.w);
                ra[4]=decf(u1.x); ra[5]=decf(u1.y); ra[6]=decf(u1.z); ra[7]=decf(u1.w);
            } else {
#pragma unroll
                for (int j = 0; j < 8; j++){
                    int kk = k + j;
                    ra[j] = (kk < 256) ? decf(apx[kk]) : ((kk < Kt) ? ap1[kk-256] : 0.f);
                }
            }
        } else {
            *(float4*)&ra[0] = *(const float4*)(ap1 + k);
            *(float4*)&ra[4] = *(const float4*)(ap1 + k + 4);
        }
    };
    auto stsA = [&](int buf){
#pragma unroll
        for (int j = 0; j < 8; j++){
            float v;
            if constexpr (MODE == 1) v = fmaxf(ra[j] - rc[j], 0.f);
            else                     v = ra[j];
            As[buf][kb + j][m_l] = v;
        }
    };
    auto cpB = [&](int kt, int buf){
        const int k0 = kt * BK;
#pragma unroll
        for (int i = 0; i < 2; i++){
            int idx = tid + i * 256;       // 0..511
            int row = idx >> 5;            // 0..15
            int c4  = idx & 31;
            int k   = k0 + row;
            if constexpr (Kt % BK == 0){
                cp_async16(&Bs[buf][row][c4*4], Bw + (size_t)k * Nt + n0 + c4*4, 16u);
            } else {
                int ks = (k < Kt) ? k : 0;
                unsigned sz = (k < Kt) ? 16u : 0u;
                cp_async16(&Bs[buf][row][c4*4], Bw + (size_t)ks * Nt + n0 + c4*4, sz);
            }
        }
        cp_commit();
    };

    float acc[8][8];
#pragma unroll
    for (int i = 0; i < 8; i++)
#pragma unroll
        for (int j = 0; j < 8; j++) acc[i][j] = 0.f;

    // prologue
    fetchA(0);
    cpB(0, 0);
    stsA(0);
    if (NKT > 1) fetchA(1);
    cp_wait0();
    __syncthreads();

    for (int kt = 0; kt < NKT; kt++){
        const int cur = kt & 1, nxt = cur ^ 1;
        if (kt + 1 < NKT) cpB(kt + 1, nxt);

#pragma unroll
        for (int kk = 0; kk < BK; kk++){
            float a[8], bfr[8];
            *(float4*)&a[0]   = *(const float4*)&As[cur][kk][ty*8];
            *(float4*)&a[4]   = *(const float4*)&As[cur][kk][ty*8 + 4];
            *(float4*)&bfr[0] = *(const float4*)&Bs[cur][kk][tx*8];
            *(float4*)&bfr[4] = *(const float4*)&Bs[cur][kk][tx*8 + 4];
#pragma unroll
            for (int i = 0; i < 8; i++)
#pragma unroll
                for (int j = 0; j < 8; j++)
                    acc[i][j] = fmaf(a[i], bfr[j], acc[i][j]);
        }

        if (kt + 1 < NKT){
            stsA(nxt);
            if (kt + 2 < NKT) fetchA(kt + 2);
            cp_wait0();
        }
        __syncthreads();
    }

    if constexpr (MODE == 1 || MODE == 3 || MODE == 4){
        float bi[8], ga[8], be[8];
#pragma unroll
        for (int j = 0; j < 8; j++){
            int n = n0 + tx*8 + j;
            bi[j] = bias[n]; ga[j] = gamma[n]; be[j] = beta[n];
        }
        float* Cout;
        if constexpr (MODE == 1) Cout = d_h2buf;
        else if constexpr (MODE == 3) Cout = d_g1;
        else Cout = d_g2;
#pragma unroll
        for (int i = 0; i < 8; i++){
            int m = m0 + ty*8 + i;
#pragma unroll
            for (int j = 0; j < 8; j++){
                int n = n0 + tx*8 + j;
                float v = fmaf(acc[i][j] + bi[j], ga[j], be[j]);
                Cout[(size_t)m * Nt + n] = fmaxf(v, 0.f);
            }
        }
    } else if constexpr (MODE == 2){
        float bi[8];
#pragma unroll
        for (int j = 0; j < 8; j++) bi[j] = bias[n0 + tx*8 + j];
#pragma unroll
        for (int i = 0; i < 8; i++){
            int m = m0 + ty*8 + i;
            int tgt = d_idx[m];
            unsigned* xp = d_xenc + tgt * 256 + n0 + tx*8;
#pragma unroll
            for (int j = 0; j < 8; j++)
                atomicMax(&xp[j], encf(acc[i][j] + bi[j]));
        }
    } else { // MODE 5
        float cm[8];
#pragma unroll
        for (int j = 0; j < 8; j++){
            float mv = acc[0][j];
#pragma unroll
            for (int i = 1; i < 8; i++) mv = fmaxf(mv, acc[i][j]);
            cm[j] = mv + bias[n0 + tx*8 + j];
        }
        __syncthreads();
#pragma unroll
        for (int j = 0; j < 8; j++) As[0][ty][tx*8 + j] = cm[j];
        __syncthreads();
        if (tid < 128){
            float mv = As[0][0][tid];
#pragma unroll
            for (int r = 1; r < 16; r++) mv = fmaxf(mv, As[0][r][tid]);
            int bb = m0 >> 12;
            atomicMax(&d_scene[bb * 1024 + n0 + tid], encf(mv));
        }
    }
}

// ---------------- predictor stage 1: h1 = relu(ef @ pw1 + pb1) ----------------
// grid (BATCH, 8); block 256. Block (b,c) computes h1[c*64 .. c*64+63].
__global__ __launch_bounds__(256) void predictor1(
    const int* __restrict__ qidx,
    const float* __restrict__ pw1, const float* __restrict__ pb1)
{
    __shared__ float ef[1280];
    __shared__ float part[256];
    int b = blockIdx.x, c = blockIdx.y, tid = threadIdx.x;
    int q = b * NPTS + qidx[b];

    if (tid < 256) ef[tid] = decf(d_xenc[q * 256 + tid]);
    for (int i = tid; i < 1024; i += 256) ef[256 + i] = decf(d_scene[b * 1024 + i]);
    __syncthreads();

    int o   = c * 64 + (tid & 63);
    int seg = tid >> 6;              // 0..3, each sums 320 k's
    float s = 0.f;
    const float* wp = pw1 + o;
#pragma unroll 4
    for (int k = seg * 320; k < seg * 320 + 320; k++)
        s = fmaf(ef[k], wp[k * 512], s);
    part[tid] = s;
    __syncthreads();
    if (tid < 64){
        float v = part[tid] + part[tid+64] + part[tid+128] + part[tid+192] + pb1[o];
        d_ph1[b * 512 + o] = fmaxf(v, 0.f);
    }
}

// ---------------- predictor stage 2 ----------------
__global__ __launch_bounds__(256) void predictor2(
    const float* __restrict__ pw2, const float* __restrict__ pb2,
    const float* __restrict__ pw3, const float* __restrict__ pb3,
    float* __restrict__ out)
{
    __shared__ float h1[512];
    __shared__ float h2[256];
    int b = blockIdx.x, tid = threadIdx.x;
    for (int i = tid; i < 512; i += 256) h1[i] = d_ph1[b * 512 + i];
    __syncthreads();
    {
        float s = pb2[tid];
#pragma unroll 4
        for (int k = 0; k < 512; k++) s = fmaf(h1[k], pw2[k*256 + tid], s);
        h2[tid] = fmaxf(s, 0.f);
    }
    __syncthreads();
    if (tid < 16){
        float s = pb3[tid];
#pragma unroll 4
        for (int k = 0; k < 256; k++) s = fmaf(h2[k], pw3[k*16 + tid], s);
        out[b*16 + tid] = s;
    }
}

// ---------------- launch ----------------
extern "C" void kernel_launch(void* const* d_in, const int* in_sizes, int n_in,
                              void* d_out, int out_size)
{
    const float* pos  = (const float*)d_in[0];
    const int*   qidx = (const int*)  d_in[1];
    const float* cw1 = (const float*)d_in[2];
    const float* cb1 = (const float*)d_in[3];
    const float* cg1 = (const float*)d_in[4];
    const float* cs1 = (const float*)d_in[5];
    const float* cw2 = (const float*)d_in[6];
    const float* cb2 = (const float*)d_in[7];
    const float* cg2 = (const float*)d_in[8];
    const float* cs2 = (const float*)d_in[9];
    const float* cw3 = (const float*)d_in[10];
    const float* cb3 = (const float*)d_in[11];
    const float* sw1 = (const float*)d_in[12];
    const float* sb1 = (const float*)d_in[13];
    const float* sg1 = (const float*)d_in[14];
    const float* ss1 = (const float*)d_in[15];
    const float* sw2 = (const float*)d_in[16];
    const float* sb2 = (const float*)d_in[17];
    const float* sg2 = (const float*)d_in[18];
    const float* ss2 = (const float*)d_in[19];
    const float* sw3 = (const float*)d_in[20];
    const float* sb3 = (const float*)d_in[21];
    const float* pw1 = (const float*)d_in[22];
    const float* pb1 = (const float*)d_in[23];
    const float* pw2 = (const float*)d_in[24];
    const float* pb2 = (const float*)d_in[25];
    const float* pw3 = (const float*)d_in[26];
    const float* pb3 = (const float*)d_in[27];

    init_kernel<<<(PTOT*256 + 255)/256, 256>>>();
    knn_kernel<<<PTOT/8, 256>>>(pos);
    prep_ac<<<(PTOT*64)/256, 256>>>(pos, cw1, cb1, cg1, cs1);

    gemm_k<1><<<dim3(1, EDGES/128), 256>>>(cw2, cb2, cg2, cs2, nullptr);
    gemm_k<2><<<dim3(2, EDGES/128), 256>>>(cw3, cb3, nullptr, nullptr, nullptr);
    gemm_k<3><<<dim3(2, PTOT/128),  256>>>(sw1, sb1, sg1, ss1, pos);
    gemm_k<4><<<dim3(4, PTOT/128),  256>>>(sw2, sb2, sg2, ss2, nullptr);
    gemm_k<5><<<dim3(8, PTOT/128),  256>>>(sw3, sb3, nullptr, nullptr, nullptr);

    predictor1<<<dim3(BATCH, 8), 256>>>(qidx, pw1, pb1);
    predictor2<<<BATCH, 256>>>(pw2, pb2, pw3, pb3, (float*)d_out);
}

// round 4
// speedup vs baseline: 2.0371x; 1.5272x over previous
#include <cuda_runtime.h>
#include <cuda_bf16.h>
#include <cstdint>
#include <cstddef>

#define BATCH 4
#define NPTS  4096
#define PTOT  (BATCH*NPTS)     /* 16384 */
#define KNN   16
#define EDGES (PTOT*KNN)       /* 262144 */
#define FLTMAX 3.402823466e+38f

// ---------------- scratch ----------------
__device__ int      d_idx[EDGES];
__device__ float    d_Ap[PTOT*64];
__device__ float    d_Cp[PTOT*64];
__device__ float    d_h2buf[(size_t)EDGES*128];
__device__ unsigned d_xenc[PTOT*256];
__device__ float    d_g1[PTOT*256];
__device__ float    d_g2[PTOT*512];
__device__ unsigned d_scene[BATCH*1024];
__device__ float    d_ph1[BATCH*512];

// split weights: [N, KPAD] bf16, hi/lo
__device__ __align__(16) __nv_bfloat16 d_w1hi[128*64],   d_w1lo[128*64];
__device__ __align__(16) __nv_bfloat16 d_w2hi[256*128],  d_w2lo[256*128];
__device__ __align__(16) __nv_bfloat16 d_w3hi[256*320],  d_w3lo[256*320];
__device__ __align__(16) __nv_bfloat16 d_w4hi[512*256],  d_w4lo[512*256];
__device__ __align__(16) __nv_bfloat16 d_w5hi[1024*512], d_w5lo[1024*512];

__device__ __forceinline__ unsigned encf(float f){
    unsigned u = __float_as_uint(f);
    return (u & 0x80000000u) ? ~u : (u | 0x80000000u);
}
__device__ __forceinline__ float decf(unsigned u){
    return __uint_as_float((u & 0x80000000u) ? (u ^ 0x80000000u) : ~u);
}

__device__ __forceinline__ uint32_t smem_u32(const void* p){
    uint32_t a;
    asm("{ .reg .u64 t; cvta.to.shared.u64 t, %1; cvt.u32.u64 %0, t; }" : "=r"(a) : "l"(p));
    return a;
}
__device__ __forceinline__ void cp_async16(void* smem, const void* gmem){
    unsigned s = (unsigned)__cvta_generic_to_shared(smem);
    asm volatile("cp.async.cg.shared.global [%0], [%1], 16;\n" :: "r"(s), "l"(gmem));
}
__device__ __forceinline__ void cp_commit(){ asm volatile("cp.async.commit_group;\n"); }
__device__ __forceinline__ void cp_wait0(){ asm volatile("cp.async.wait_group 0;\n"); }

__device__ __forceinline__ void ldm_x4(uint32_t& r0, uint32_t& r1, uint32_t& r2, uint32_t& r3, uint32_t addr){
    asm volatile("ldmatrix.sync.aligned.m8n8.x4.shared.b16 {%0,%1,%2,%3}, [%4];"
        : "=r"(r0), "=r"(r1), "=r"(r2), "=r"(r3) : "r"(addr));
}
__device__ __forceinline__ void mma_bf16(float* c, const uint32_t* a, const uint32_t* b){
    asm volatile(
        "mma.sync.aligned.m16n8k16.row.col.f32.bf16.bf16.f32 "
        "{%0,%1,%2,%3}, {%4,%5,%6,%7}, {%8,%9}, {%0,%1,%2,%3};"
        : "+f"(c[0]), "+f"(c[1]), "+f"(c[2]), "+f"(c[3])
        : "r"(a[0]), "r"(a[1]), "r"(a[2]), "r"(a[3]), "r"(b[0]), "r"(b[1]));
}
__device__ __forceinline__ uint32_t pk2(__nv_bfloat16 a, __nv_bfloat16 b){
    return (uint32_t)__bfloat16_as_ushort(a) | ((uint32_t)__bfloat16_as_ushort(b) << 16);
}

// ---------------- init ----------------
__global__ void init_kernel(){
    int i = blockIdx.x * 256 + threadIdx.x;
    if (i < PTOT*256)   d_xenc[i]  = 0x00800000u;
    if (i < BATCH*1024) d_scene[i] = 0x00800000u;
}

// ---------------- kNN ----------------
__global__ __launch_bounds__(256) void knn_kernel(const float* __restrict__ pos){
    __shared__ float sbuf[3*NPTS];
    float* sx = sbuf; float* sy = sbuf + NPTS; float* sz = sbuf + 2*NPTS;
    int b  = blockIdx.x >> 9;
    int s0 = (blockIdx.x & 511) * 8;
    const float* pb = pos + (size_t)b * NPTS * 3;
    for (int i = threadIdx.x; i < NPTS; i += 256){
        sx[i] = pb[3*i]; sy[i] = pb[3*i+1]; sz[i] = pb[3*i+2];
    }
    __syncthreads();
    int w = threadIdx.x >> 5, lane = threadIdx.x & 31;
    int src = s0 + w;
    float qx = sx[src], qy = sy[src], qz = sz[src];
    float ld[KNN]; int li[KNN];
#pragma unroll
    for (int j = 0; j < KNN; j++){ ld[j] = FLTMAX; li[j] = 1<<30; }
    for (int c = lane; c < NPTS; c += 32){
        float dx = qx - sx[c], dy = qy - sy[c], dz = qz - sz[c];
        float d = __fadd_rn(__fadd_rn(__fmul_rn(dx,dx), __fmul_rn(dy,dy)), __fmul_rn(dz,dz));
        if (d < ld[KNN-1] || (d == ld[KNN-1] && c < li[KNN-1])){
            ld[KNN-1] = d; li[KNN-1] = c;
#pragma unroll
            for (int j = KNN-1; j > 0; j--){
                bool sw = (ld[j] < ld[j-1]) || (ld[j] == ld[j-1] && li[j] < li[j-1]);
                if (sw){
                    float td = ld[j]; ld[j] = ld[j-1]; ld[j-1] = td;
                    int   ti = li[j]; li[j] = li[j-1]; li[j-1] = ti;
                }
            }
        }
    }
    __syncthreads();
    float* smd = sbuf;
    int*   smi = (int*)(sbuf + 4096);
    int base = (w*32 + lane) * KNN;
#pragma unroll
    for (int j = 0; j < KNN; j++){ smd[base+j] = ld[j]; smi[base+j] = li[j]; }
    __syncwarp();
    int ptr = 0;
    int outbase = (b*NPTS + src) * KNN;
    for (int r = 0; r < KNN; r++){
        float myd = (ptr < KNN) ? smd[base+ptr] : FLTMAX;
        int   myi = (ptr < KNN) ? smi[base+ptr] : (1<<30);
        float bd = myd; int bi = myi;
#pragma unroll
        for (int off = 16; off; off >>= 1){
            float od = __shfl_xor_sync(0xffffffffu, bd, off);
            int   oi = __shfl_xor_sync(0xffffffffu, bi, off);
            if (od < bd || (od == bd && oi < bi)){ bd = od; bi = oi; }
        }
        if (myd == bd && myi == bi) ptr++;
        if (lane == 0) d_idx[outbase + r] = b*NPTS + bi;
    }
}

// ---------------- fold layer-1 + BN ----------------
__global__ void prep_ac(const float* __restrict__ pos, const float* __restrict__ cw1,
                        const float* __restrict__ cb1, const float* __restrict__ cg1,
                        const float* __restrict__ cs1){
    int gi = blockIdx.x * 256 + threadIdx.x;
    int p = gi >> 6, j = gi & 63;
    float x = pos[p*3], y = pos[p*3+1], z = pos[p*3+2];
    float w0 = cw1[0*64+j] + cw1[3*64+j];
    float w1 = cw1[1*64+j] + cw1[4*64+j];
    float w2 = cw1[2*64+j] + cw1[5*64+j];
    float a = fmaf(x, w0, fmaf(y, w1, fmaf(z, w2, cb1[j])));
    float c = fmaf(x, cw1[3*64+j], fmaf(y, cw1[4*64+j], z*cw1[5*64+j]));
    float g = cg1[j];
    d_Ap[gi] = fmaf(a, g, cs1[j]);
    d_Cp[gi] = c * g;
}

// ---------------- weight transpose + bf16 split: W[Kt,Nt] -> Whi/Wlo[Nt,KPAD] ----------------
__global__ void prep_w(const float* __restrict__ W, __nv_bfloat16* __restrict__ hi,
                       __nv_bfloat16* __restrict__ lo, int Kt, int Nt, int KPAD){
    int idx = blockIdx.x * 256 + threadIdx.x;
    int n = idx / KPAD, k = idx % KPAD;
    float v = (k < Kt) ? W[(size_t)k * Nt + n] : 0.f;
    __nv_bfloat16 h = __float2bfloat16(v);
    hi[idx] = h;
    lo[idx] = __float2bfloat16(v - __bfloat162float(h));
}

// ---------------- mma.sync bf16 split GEMM with fused A-gen + epilogues ----------------
// Tile: 128x128, BK=32, 8 warps (2x4), warp tile 64x32.
// smem rows padded to 40 bf16 (80B) for conflict-free ldmatrix.
// MODE 1: h2 = relu(bn(edge_h1 @ cw2))         M=EDGES Nt=128  KPAD=64
// MODE 2: m  = h2 @ cw3 + b ; scatter-max      M=EDGES Nt=256  KPAD=128
// MODE 3: g1 = relu(bn(g0 @ sw1))              M=PTOT  Nt=256  KPAD=320
// MODE 4: g2 = relu(bn(g1 @ sw2))              M=PTOT  Nt=512  KPAD=256
// MODE 5: g3 = g2 @ sw3 + b ; scene-max        M=PTOT  Nt=1024 KPAD=512
#define TB 10240                 /* one tile: 128 rows * 80B */
#define SMEM_REQ (8*TB)          /* 81920 */

template<int MODE>
__global__ __launch_bounds__(256, 1)
void gemm_mm(const __nv_bfloat16* __restrict__ whi, const __nv_bfloat16* __restrict__ wlo,
             const float* __restrict__ bias, const float* __restrict__ gamma,
             const float* __restrict__ beta, const float* __restrict__ pos)
{
    constexpr int Nt   = (MODE==1)?128:(MODE==2)?256:(MODE==3)?256:(MODE==4)?512:1024;
    constexpr int Kt   = (MODE==1)?64:(MODE==2)?128:(MODE==3)?259:(MODE==4)?256:512;
    constexpr int KPAD = (MODE==3)?320:((Kt+31)&~31);
    constexpr int NCH  = KPAD/32;

    extern __shared__ char dsm[];
    const uint32_t sb = smem_u32(dsm);

    const int tid  = threadIdx.x;
    const int lane = tid & 31;
    const int warp = tid >> 5;
    const int wr = warp >> 2;       // 0..1  (64-row slab)
    const int wc = warp & 3;        // 0..3  (32-col slab)
    const int m0 = blockIdx.y * 128;
    const int n0 = blockIdx.x * 128;

    // loader mapping: row lr = tid>>1, 16 cols starting at (tid&1)*16
    const int lr  = tid >> 1;
    const int lc0 = (tid & 1) * 16;
    const int am  = m0 + lr;
    int tgt1 = 0;
    if constexpr (MODE == 1) tgt1 = d_idx[am];

    // smem byte offsets
    auto AH = [&](int buf){ return (uint32_t)(buf*TB); };
    auto AL = [&](int buf){ return (uint32_t)(2*TB + buf*TB); };
    auto BH = [&](int buf){ return (uint32_t)(4*TB + buf*TB); };
    auto BL = [&](int buf){ return (uint32_t)(6*TB + buf*TB); };

    float v[16];
    auto fetchA = [&](int ch){
        const int k = ch*32 + lc0;
        if constexpr (MODE == 1){
            const float* p1 = d_Ap + (size_t)(am >> 4) * 64 + k;
            const float* p2 = d_Cp + (size_t)tgt1 * 64 + k;
#pragma unroll
            for (int q = 0; q < 4; q++){
                float4 a = *(const float4*)(p1 + q*4);
                float4 c = *(const float4*)(p2 + q*4);
                v[q*4+0] = fmaxf(a.x - c.x, 0.f);
                v[q*4+1] = fmaxf(a.y - c.y, 0.f);
                v[q*4+2] = fmaxf(a.z - c.z, 0.f);
                v[q*4+3] = fmaxf(a.w - c.w, 0.f);
            }
        } else if constexpr (MODE == 3){
            if (k + 15 < 256){
                const unsigned* p = d_xenc + (size_t)am * 256 + k;
#pragma unroll
                for (int q = 0; q < 4; q++){
                    uint4 u = *(const uint4*)(p + q*4);
                    v[q*4+0]=decf(u.x); v[q*4+1]=decf(u.y); v[q*4+2]=decf(u.z); v[q*4+3]=decf(u.w);
                }
            } else {
#pragma unroll
                for (int j = 0; j < 16; j++){
                    int kk = k + j;
                    v[j] = (kk < 256) ? decf(d_xenc[(size_t)am*256 + kk])
                         : ((kk < 259) ? pos[(size_t)am*3 + (kk-256)] : 0.f);
                }
            }
        } else {
            const float* p = (MODE==2) ? d_h2buf + (size_t)am * 128 + k
                          : (MODE==4) ? d_g1 + (size_t)am * 256 + k
                          :             d_g2 + (size_t)am * 512 + k;
#pragma unroll
            for (int q = 0; q < 4; q++){
                float4 a = *(const float4*)(p + q*4);
                v[q*4+0]=a.x; v[q*4+1]=a.y; v[q*4+2]=a.z; v[q*4+3]=a.w;
            }
        }
    };
    auto stsA = [&](int buf){
        __nv_bfloat16 h[16], l[16];
#pragma unroll
        for (int j = 0; j < 16; j++){
            h[j] = __float2bfloat16(v[j]);
            l[j] = __float2bfloat16(v[j] - __bfloat162float(h[j]));
        }
        const uint32_t off = (uint32_t)lr*80 + (uint32_t)lc0*2;
        *(uint4*)(dsm + AH(buf) + off)      = make_uint4(pk2(h[0],h[1]), pk2(h[2],h[3]), pk2(h[4],h[5]), pk2(h[6],h[7]));
        *(uint4*)(dsm + AH(buf) + off + 16) = make_uint4(pk2(h[8],h[9]), pk2(h[10],h[11]), pk2(h[12],h[13]), pk2(h[14],h[15]));
        *(uint4*)(dsm + AL(buf) + off)      = make_uint4(pk2(l[0],l[1]), pk2(l[2],l[3]), pk2(l[4],l[5]), pk2(l[6],l[7]));
        *(uint4*)(dsm + AL(buf) + off + 16) = make_uint4(pk2(l[8],l[9]), pk2(l[10],l[11]), pk2(l[12],l[13]), pk2(l[14],l[15]));
    };
    auto cpB = [&](int ch, int buf){
#pragma unroll
        for (int i = 0; i < 2; i++){
            int idx = tid + i*256;
            int row = idx >> 2, c = idx & 3;
            const __nv_bfloat16* gh = whi + (size_t)(n0 + row) * KPAD + ch*32 + c*8;
            const __nv_bfloat16* gl = wlo + (size_t)(n0 + row) * KPAD + ch*32 + c*8;
            cp_async16(dsm + BH(buf) + row*80 + c*16, gh);
            cp_async16(dsm + BL(buf) + row*80 + c*16, gl);
        }
        cp_commit();
    };

    float acc[4][4][4];
#pragma unroll
    for (int mt = 0; mt < 4; mt++)
#pragma unroll
        for (int nt = 0; nt < 4; nt++)
#pragma unroll
            for (int e = 0; e < 4; e++) acc[mt][nt][e] = 0.f;

    // prologue
    fetchA(0);
    cpB(0, 0);
    stsA(0);
    if (NCH > 1) fetchA(1);
    cp_wait0();
    __syncthreads();

    for (int ch = 0; ch < NCH; ch++){
        const int cur = ch & 1, nxt = cur ^ 1;
        if (ch + 1 < NCH) cpB(ch + 1, nxt);

        const uint32_t uAH = sb + AH(cur), uAL = sb + AL(cur);
        const uint32_t uBH = sb + BH(cur), uBL = sb + BL(cur);
        const int arow = wr*64 + (lane & 15);
        const int brow = wc*32 + (lane & 7) + (((lane >> 4) & 1) << 3);

#pragma unroll
        for (int ks = 0; ks < 2; ks++){
            const int k0 = ks * 16;
            const uint32_t acol = (uint32_t)(k0 + ((lane >> 4) << 3)) * 2;
            const uint32_t bcol = (uint32_t)(k0 + (((lane >> 3) & 1) << 3)) * 2;
            uint32_t ah[4][4], al[4][4];
#pragma unroll
            for (int mt = 0; mt < 4; mt++){
                uint32_t ad = uAH + (uint32_t)(arow + mt*16)*80 + acol;
                ldm_x4(ah[mt][0], ah[mt][1], ah[mt][2], ah[mt][3], ad);
                uint32_t ad2 = uAL + (uint32_t)(arow + mt*16)*80 + acol;
                ldm_x4(al[mt][0], al[mt][1], al[mt][2], al[mt][3], ad2);
            }
#pragma unroll
            for (int np = 0; np < 2; np++){
                uint32_t bh[4], bl[4];
                uint32_t bd = uBH + (uint32_t)(brow + np*16)*80 + bcol;
                ldm_x4(bh[0], bh[1], bh[2], bh[3], bd);
                uint32_t bd2 = uBL + (uint32_t)(brow + np*16)*80 + bcol;
                ldm_x4(bl[0], bl[1], bl[2], bl[3], bd2);
#pragma unroll
                for (int mt = 0; mt < 4; mt++){
                    mma_bf16(acc[mt][np*2],   ah[mt], &bh[0]);
                    mma_bf16(acc[mt][np*2],   al[mt], &bh[0]);
                    mma_bf16(acc[mt][np*2],   ah[mt], &bl[0]);
                    mma_bf16(acc[mt][np*2+1], ah[mt], &bh[2]);
                    mma_bf16(acc[mt][np*2+1], al[mt], &bh[2]);
                    mma_bf16(acc[mt][np*2+1], ah[mt], &bl[2]);
                }
            }
        }

        if (ch + 1 < NCH){
            stsA(nxt);
            if (ch + 2 < NCH) fetchA(ch + 2);
            cp_wait0();
        }
        __syncthreads();
    }

    // ---------------- epilogue ----------------
    const int g  = lane >> 2;
    const int tg = lane & 3;

    if constexpr (MODE == 1 || MODE == 3 || MODE == 4){
        float* Cout = (MODE==1) ? d_h2buf : (MODE==3) ? d_g1 : d_g2;
#pragma unroll
        for (int nt = 0; nt < 4; nt++){
            const int n = n0 + wc*32 + nt*8 + tg*2;
            const float b0 = __ldg(bias+n),  b1 = __ldg(bias+n+1);
            const float g0 = __ldg(gamma+n), g1v = __ldg(gamma+n+1);
            const float e0 = __ldg(beta+n),  e1 = __ldg(beta+n+1);
#pragma unroll
            for (int mt = 0; mt < 4; mt++){
                const int r0 = m0 + wr*64 + mt*16 + g;
                float2 o0, o1;
                o0.x = fmaxf(fmaf(acc[mt][nt][0] + b0, g0, e0), 0.f);
                o0.y = fmaxf(fmaf(acc[mt][nt][1] + b1, g1v, e1), 0.f);
                o1.x = fmaxf(fmaf(acc[mt][nt][2] + b0, g0, e0), 0.f);
                o1.y = fmaxf(fmaf(acc[mt][nt][3] + b1, g1v, e1), 0.f);
                *(float2*)(Cout + (size_t)r0 * Nt + n)       = o0;
                *(float2*)(Cout + (size_t)(r0+8) * Nt + n)   = o1;
            }
        }
    } else if constexpr (MODE == 2){
#pragma unroll
        for (int mt = 0; mt < 4; mt++){
            const int r0 = m0 + wr*64 + mt*16 + g;
            const int tA = d_idx[r0], tB = d_idx[r0 + 8];
#pragma unroll
            for (int nt = 0; nt < 4; nt++){
                const int n = n0 + wc*32 + nt*8 + tg*2;
                const float b0 = __ldg(bias+n), b1 = __ldg(bias+n+1);
                atomicMax(d_xenc + (size_t)tA*256 + n,     encf(acc[mt][nt][0] + b0));
                atomicMax(d_xenc + (size_t)tA*256 + n + 1, encf(acc[mt][nt][1] + b1));
                atomicMax(d_xenc + (size_t)tB*256 + n,     encf(acc[mt][nt][2] + b0));
                atomicMax(d_xenc + (size_t)tB*256 + n + 1, encf(acc[mt][nt][3] + b1));
            }
        }
    } else { // MODE 5
        float* sc = (float*)dsm;   // 256 floats scratch (tiles dead)
#pragma unroll
        for (int nt = 0; nt < 4; nt++){
#pragma unroll
            for (int cp = 0; cp < 2; cp++){
                float mv = fmaxf(acc[0][nt][cp], acc[0][nt][cp+2]);
#pragma unroll
                for (int mt = 1; mt < 4; mt++)
                    mv = fmaxf(mv, fmaxf(acc[mt][nt][cp], acc[mt][nt][cp+2]));
#pragma unroll
                for (int off = 4; off < 32; off <<= 1)
                    mv = fmaxf(mv, __shfl_xor_sync(0xffffffffu, mv, off));
                if (g == 0) sc[wr*128 + wc*32 + nt*8 + tg*2 + cp] = mv;
            }
        }
        __syncthreads();
        if (tid < 128){
            float mv = fmaxf(sc[tid], sc[128 + tid]) + __ldg(bias + n0 + tid);
            int bb = m0 >> 12;
            atomicMax(&d_scene[bb * 1024 + n0 + tid], encf(mv));
        }
    }
}

// ---------------- predictor stage 1 ----------------
__global__ __launch_bounds__(256) void predictor1(
    const int* __restrict__ qidx,
    const float* __restrict__ pw1, const float* __restrict__ pb1)
{
    __shared__ float ef[1280];
    __shared__ float part[256];
    int b = blockIdx.x, c = blockIdx.y, tid = threadIdx.x;
    int q = b * NPTS + qidx[b];
    if (tid < 256) ef[tid] = decf(d_xenc[q * 256 + tid]);
    for (int i = tid; i < 1024; i += 256) ef[256 + i] = decf(d_scene[b * 1024 + i]);
    __syncthreads();
    int o   = c * 64 + (tid & 63);
    int seg = tid >> 6;
    float s = 0.f;
    const float* wp = pw1 + o;
#pragma unroll 4
    for (int k = seg * 320; k < seg * 320 + 320; k++)
        s = fmaf(ef[k], wp[k * 512], s);
    part[tid] = s;
    __syncthreads();
    if (tid < 64){
        float vv = part[tid] + part[tid+64] + part[tid+128] + part[tid+192] + pb1[o];
        d_ph1[b * 512 + o] = fmaxf(vv, 0.f);
    }
}

// ---------------- predictor stage 2 ----------------
__global__ __launch_bounds__(256) void predictor2(
    const float* __restrict__ pw2, const float* __restrict__ pb2,
    const float* __restrict__ pw3, const float* __restrict__ pb3,
    float* __restrict__ out)
{
    __shared__ float h1[512];
    __shared__ float h2[256];
    int b = blockIdx.x, tid = threadIdx.x;
    for (int i = tid; i < 512; i += 256) h1[i] = d_ph1[b * 512 + i];
    __syncthreads();
    {
        float s = pb2[tid];
#pragma unroll 4
        for (int k = 0; k < 512; k++) s = fmaf(h1[k], pw2[k*256 + tid], s);
        h2[tid] = fmaxf(s, 0.f);
    }
    __syncthreads();
    if (tid < 16){
        float s = pb3[tid];
#pragma unroll 4
        for (int k = 0; k < 256; k++) s = fmaf(h2[k], pw3[k*16 + tid], s);
        out[b*16 + tid] = s;
    }
}

// ---------------- launch ----------------
extern "C" void kernel_launch(void* const* d_in, const int* in_sizes, int n_in,
                              void* d_out, int out_size)
{
    const float* pos  = (const float*)d_in[0];
    const int*   qidx = (const int*)  d_in[1];
    const float* cw1 = (const float*)d_in[2];
    const float* cb1 = (const float*)d_in[3];
    const float* cg1 = (const float*)d_in[4];
    const float* cs1 = (const float*)d_in[5];
    const float* cw2 = (const float*)d_in[6];
    const float* cb2 = (const float*)d_in[7];
    const float* cg2 = (const float*)d_in[8];
    const float* cs2 = (const float*)d_in[9];
    const float* cw3 = (const float*)d_in[10];
    const float* cb3 = (const float*)d_in[11];
    const float* sw1 = (const float*)d_in[12];
    const float* sb1 = (const float*)d_in[13];
    const float* sg1 = (const float*)d_in[14];
    const float* ss1 = (const float*)d_in[15];
    const float* sw2 = (const float*)d_in[16];
    const float* sb2 = (const float*)d_in[17];
    const float* sg2 = (const float*)d_in[18];
    const float* ss2 = (const float*)d_in[19];
    const float* sw3 = (const float*)d_in[20];
    const float* sb3 = (const float*)d_in[21];
    const float* pw1 = (const float*)d_in[22];
    const float* pb1 = (const float*)d_in[23];
    const float* pw2 = (const float*)d_in[24];
    const float* pb2 = (const float*)d_in[25];
    const float* pw3 = (const float*)d_in[26];
    const float* pb3 = (const float*)d_in[27];

    cudaFuncSetAttribute(gemm_mm<1>, cudaFuncAttributeMaxDynamicSharedMemorySize, SMEM_REQ);
    cudaFuncSetAttribute(gemm_mm<2>, cudaFuncAttributeMaxDynamicSharedMemorySize, SMEM_REQ);
    cudaFuncSetAttribute(gemm_mm<3>, cudaFuncAttributeMaxDynamicSharedMemorySize, SMEM_REQ);
    cudaFuncSetAttribute(gemm_mm<4>, cudaFuncAttributeMaxDynamicSharedMemorySize, SMEM_REQ);
    cudaFuncSetAttribute(gemm_mm<5>, cudaFuncAttributeMaxDynamicSharedMemorySize, SMEM_REQ);

    init_kernel<<<(PTOT*256 + 255)/256, 256>>>();
    knn_kernel<<<PTOT/8, 256>>>(pos);
    prep_ac<<<(PTOT*64)/256, 256>>>(pos, cw1, cb1, cg1, cs1);

    __nv_bfloat16 *w1h, *w1l, *w2h, *w2l, *w3h, *w3l, *w4h, *w4l, *w5h, *w5l;
    cudaGetSymbolAddress((void**)&w1h, d_w1hi); cudaGetSymbolAddress((void**)&w1l, d_w1lo);
    cudaGetSymbolAddress((void**)&w2h, d_w2hi); cudaGetSymbolAddress((void**)&w2l, d_w2lo);
    cudaGetSymbolAddress((void**)&w3h, d_w3hi); cudaGetSymbolAddress((void**)&w3l, d_w3lo);
    cudaGetSymbolAddress((void**)&w4h, d_w4hi); cudaGetSymbolAddress((void**)&w4l, d_w4lo);
    cudaGetSymbolAddress((void**)&w5h, d_w5hi); cudaGetSymbolAddress((void**)&w5l, d_w5lo);

    prep_w<<<(128*64)/256,   256>>>(cw2, w1h, w1l, 64, 128, 64);
    prep_w<<<(256*128)/256,  256>>>(cw3, w2h, w2l, 128, 256, 128);
    prep_w<<<(256*320)/256,  256>>>(sw1, w3h, w3l, 259, 256, 320);
    prep_w<<<(512*256)/256,  256>>>(sw2, w4h, w4l, 256, 512, 256);
    prep_w<<<(1024*512)/256, 256>>>(sw3, w5h, w5l, 512, 1024, 512);

    gemm_mm<1><<<dim3(1, EDGES/128), 256, SMEM_REQ>>>(w1h, w1l, cb2, cg2, cs2, nullptr);
    gemm_mm<2><<<dim3(2, EDGES/128), 256, SMEM_REQ>>>(w2h, w2l, cb3, nullptr, nullptr, nullptr);
    gemm_mm<3><<<dim3(2, PTOT/128),  256, SMEM_REQ>>>(w3h, w3l, sb1, sg1, ss1, pos);
    gemm_mm<4><<<dim3(4, PTOT/128),  256, SMEM_REQ>>>(w4h, w4l, sb2, sg2, ss2, nullptr);
    gemm_mm<5><<<dim3(8, PTOT/128),  256, SMEM_REQ>>>(w5h, w5l, sb3, nullptr, nullptr, nullptr);

    predictor1<<<dim3(BATCH, 8), 256>>>(qidx, pw1, pb1);
    predictor2<<<BATCH, 256>>>(pw2, pb2, pw3, pb3, (float*)d_out);
}